// round 7
// baseline (speedup 1.0000x reference)
#include <cuda_runtime.h>
#include <cstdint>

// Shapes (fixed by reference setup_inputs)
#define NROWS 16384   // B*L = 8*2048
#define DDIM  512
#define DC    16
#define KCB   8192
#define LN_EPS 1e-5f
#define RPW   4       // rows per warp

// One kernel, no device globals, no atomics, no shared memory, no PTX.
// 8 warps/block, 4 rows/warp -> 32 rows/block, 512 blocks.
__global__ void __launch_bounds__(256) rpq_kernel(
    const float* __restrict__ x,      // (NROWS, DDIM)
    const float* __restrict__ W,      // (DC, DDIM)
    const float* __restrict__ cb,     // (KCB, DC)
    float* __restrict__ out)          // (NROWS) -- codes as FLOAT32
{
    const int warp = threadIdx.x >> 5;
    const int lane = threadIdx.x & 31;
    const int rowBase = (blockIdx.x * 8 + warp) * RPW;

    // ---- Phase A: projection + LayerNorm for RPW rows (warp-cooperative) ----
    float h[RPW][DC];      // normalized h, replicated across all lanes
    float h2[RPW];         // sum h^2 per row

#pragma unroll
    for (int r = 0; r < RPW; r++) {
        const int row = rowBase + r;
        float acc[DC];
#pragma unroll
        for (int j = 0; j < DC; j++) acc[j] = 0.f;

        const float* xrow = x + (size_t)row * DDIM;
#pragma unroll 4
        for (int d = lane; d < DDIM; d += 32) {
            float xv = xrow[d];                          // coalesced
#pragma unroll
            for (int j = 0; j < DC; j++)
                acc[j] = fmaf(xv, W[j * DDIM + d], acc[j]);   // W: 32KB, L1-hot
        }
        // butterfly-reduce the 16 sums; all lanes end with the full values
#pragma unroll
        for (int j = 0; j < DC; j++) {
#pragma unroll
            for (int ofs = 16; ofs > 0; ofs >>= 1)
                acc[j] += __shfl_xor_sync(0xFFFFFFFFu, acc[j], ofs);
        }

        // LayerNorm (correctly-rounded ops: sqrtf + division)
        float s = 0.f;
#pragma unroll
        for (int j = 0; j < DC; j++) s += acc[j];
        float mu = s * (1.0f / DC);
        float v = 0.f;
#pragma unroll
        for (int j = 0; j < DC; j++) { float d = acc[j] - mu; v = fmaf(d, d, v); }
        float denom = sqrtf(v * (1.0f / DC) + LN_EPS);
#pragma unroll
        for (int j = 0; j < DC; j++) h[r][j] = (acc[j] - mu) / denom;

        float q = 0.f;
#pragma unroll
        for (int j = 0; j < DC; j++) q = fmaf(h[r][j], h[r][j], q);
        h2[r] = q;
    }

    // ---- Phase B: argmin_k of (h2 - 2*dot) + c2, lane-strided over k ----
    float best[RPW];
    int   bidx[RPW];
#pragma unroll
    for (int r = 0; r < RPW; r++) { best[r] = 3.4e38f; bidx[r] = 0x7FFFFFFF; }

    for (int k = lane; k < KCB; k += 32) {               // coalesced: 2KB/warp/iter
        const float4* c4 = (const float4*)(cb + (size_t)k * DC);
        float4 a = c4[0], b = c4[1], c = c4[2], d = c4[3];
        float cv[DC] = {a.x, a.y, a.z, a.w, b.x, b.y, b.z, b.w,
                        c.x, c.y, c.z, c.w, d.x, d.y, d.z, d.w};
        float c2 = 0.f;
#pragma unroll
        for (int j = 0; j < DC; j++) c2 = fmaf(cv[j], cv[j], c2);

#pragma unroll
        for (int r = 0; r < RPW; r++) {
            float dot = 0.f;
#pragma unroll
            for (int j = 0; j < DC; j++) dot = fmaf(h[r][j], cv[j], dot);
            float dist = (h2[r] - 2.0f * dot) + c2;      // reference order
            if (dist < best[r]) { best[r] = dist; bidx[r] = k; }  // first-min
        }
    }

    // cross-lane merge: min value, ties -> smaller index (JAX first-min)
#pragma unroll
    for (int r = 0; r < RPW; r++) {
#pragma unroll
        for (int ofs = 16; ofs > 0; ofs >>= 1) {
            float v2 = __shfl_xor_sync(0xFFFFFFFFu, best[r], ofs);
            int   i2 = __shfl_xor_sync(0xFFFFFFFFu, bidx[r], ofs);
            if (v2 < best[r] || (v2 == best[r] && i2 < bidx[r])) {
                best[r] = v2; bidx[r] = i2;
            }
        }
        if (lane == 0) out[rowBase + r] = (float)bidx[r];   // code as float32
    }
}

extern "C" void kernel_launch(void* const* d_in, const int* in_sizes, int n_in,
                              void* d_out, int out_size) {
    // Rank inputs by size (robust whether element counts or bytes):
    // x (8388608 el) > codebook (131072 el) > proj_weight (8192 el)
    int a = 0, b = 1, c = 2;
    if (n_in >= 3) {
        if (in_sizes[a] < in_sizes[b]) { int t = a; a = b; b = t; }
        if (in_sizes[b] < in_sizes[c]) { int t = b; b = c; c = t; }
        if (in_sizes[a] < in_sizes[b]) { int t = a; a = b; b = t; }
    }
    const float* x  = (const float*)d_in[a];
    const float* cb = (const float*)d_in[b];
    const float* W  = (const float*)d_in[c];
    float* out = (float*)d_out;

    rpq_kernel<<<NROWS / 32, 256>>>(x, W, cb, out);

    // Diagnostic fallback: if the launch itself failed (e.g. no kernel image
    // for this device), stamp a distinctive all-0xFF (NaN) pattern so the
    // failure mode is distinguishable from "kernel ran but wrong".
    cudaError_t err = cudaGetLastError();
    if (err != cudaSuccess) {
        cudaMemsetAsync(d_out, 0xFF, (size_t)out_size * sizeof(float));
    }
}

// round 8
// speedup vs baseline: 1.7163x; 1.7163x over previous
#include <cuda_runtime.h>
#include <cstdint>

// Shapes (fixed by reference setup_inputs)
#define NROWS 16384   // B*L = 8*2048
#define DDIM  512
#define DC    16
#define KCB   8192
#define LN_EPS 1e-5f

// ---------------- device scratch (no allocation allowed) --------------------
__device__ float4             g_h4[NROWS * 4];    // LN(h) per row as 4x float4 (1 MB)
__device__ float              g_h2[NROWS];        // sum h^2 per row
__device__ float              g_c2[KCB];          // sum c^2 per code (exact fmaf chain)
__device__ unsigned long long g_best[NROWS];      // packed (ordered_score<<32)|idx

__device__ __forceinline__ unsigned ordered_u32(float f) {
    unsigned u = __float_as_uint(f);
    return (u & 0x80000000u) ? ~u : (u | 0x80000000u);
}

// ---------------- kernel 0: init (every launch; graph replays) --------------
__global__ void k_init(const float* __restrict__ cb) {
    int i = blockIdx.x * blockDim.x + threadIdx.x;
    if (i < NROWS) g_best[i] = 0xFFFFFFFFFFFFFFFFull;
    if (i < KCB) {
        const float4* c4 = (const float4*)(cb + (size_t)i * DC);
        float4 a = c4[0], b = c4[1], c = c4[2], d = c4[3];
        float cv[DC] = {a.x, a.y, a.z, a.w, b.x, b.y, b.z, b.w,
                        c.x, c.y, c.z, c.w, d.x, d.y, d.z, d.w};
        float c2 = 0.f;
#pragma unroll
        for (int j = 0; j < DC; j++) c2 = fmaf(cv[j], cv[j], c2);  // same chain as R7
        g_c2[i] = c2;
    }
}

// ---------------- kernel 1: projection + LayerNorm (bit-identical to R7) ----
// One warp per 4 rows; 8 warps/block; 512 blocks.
__global__ void __launch_bounds__(256) k_proj(
    const float* __restrict__ x, const float* __restrict__ W)
{
    const int warp = threadIdx.x >> 5;
    const int lane = threadIdx.x & 31;
    const int rowBase = (blockIdx.x * 8 + warp) * 4;

#pragma unroll
    for (int r = 0; r < 4; r++) {
        const int row = rowBase + r;
        float acc[DC];
#pragma unroll
        for (int j = 0; j < DC; j++) acc[j] = 0.f;

        const float* xrow = x + (size_t)row * DDIM;
#pragma unroll 4
        for (int d = lane; d < DDIM; d += 32) {
            float xv = xrow[d];
#pragma unroll
            for (int j = 0; j < DC; j++)
                acc[j] = fmaf(xv, W[j * DDIM + d], acc[j]);
        }
#pragma unroll
        for (int j = 0; j < DC; j++) {
#pragma unroll
            for (int ofs = 16; ofs > 0; ofs >>= 1)
                acc[j] += __shfl_xor_sync(0xFFFFFFFFu, acc[j], ofs);
        }

        float s = 0.f;
#pragma unroll
        for (int j = 0; j < DC; j++) s += acc[j];
        float mu = s * (1.0f / DC);
        float v = 0.f;
#pragma unroll
        for (int j = 0; j < DC; j++) { float d = acc[j] - mu; v = fmaf(d, d, v); }
        float denom = sqrtf(v * (1.0f / DC) + LN_EPS);
        float h[DC];
#pragma unroll
        for (int j = 0; j < DC; j++) h[j] = (acc[j] - mu) / denom;

        float q = 0.f;
#pragma unroll
        for (int j = 0; j < DC; j++) q = fmaf(h[j], h[j], q);

        if (lane < 4)
            g_h4[(size_t)row * 4 + lane] =
                make_float4(h[4 * lane], h[4 * lane + 1], h[4 * lane + 2], h[4 * lane + 3]);
        if (lane == 0) g_h2[row] = q;
    }
}

// ---------------- kernel 2: distance + argmin (split-K, register-tiled) -----
// grid (32, 16): bx = 512-row tile, by = 512-code chunk. 128 thr, 4 rows/thr.
// Score arithmetic is bit-identical to R7: ascending-j fmaf dot,
// dist = (h2 - 2*dot) + c2, strict < with ascending k.
__global__ void __launch_bounds__(128, 4) k_dist(const float4* __restrict__ cb4) {
    __shared__ float4 cs[512 * 4];   // 512 codes x 16 floats (32 KB)
    __shared__ float  c2s[512];

    const int tid = threadIdx.x;
    const int rowBase  = blockIdx.x * 512;
    const int codeBase = blockIdx.y * 512;

    for (int i = tid; i < 512 * 4; i += 128) cs[i] = cb4[codeBase * 4 + i];
    for (int i = tid; i < 512; i += 128) c2s[i] = g_c2[codeBase + i];
    __syncthreads();

    // this thread's 4 rows of h (register-resident)
    float h[4][DC];
    float h2[4];
#pragma unroll
    for (int r = 0; r < 4; r++) {
        const int row = rowBase + r * 128 + tid;
        const float4* p = &g_h4[(size_t)row * 4];
#pragma unroll
        for (int q = 0; q < 4; q++) {
            float4 a = p[q];
            h[r][4 * q + 0] = a.x; h[r][4 * q + 1] = a.y;
            h[r][4 * q + 2] = a.z; h[r][4 * q + 3] = a.w;
        }
        h2[r] = g_h2[row];
    }

    float best[4] = {3.4e38f, 3.4e38f, 3.4e38f, 3.4e38f};
    int   bidx[4] = {0x7FFFFFFF, 0x7FFFFFFF, 0x7FFFFFFF, 0x7FFFFFFF};

    for (int k = 0; k < 512; k++) {                 // all threads same k: broadcast LDS
        float4 a = cs[k * 4 + 0], b = cs[k * 4 + 1];
        float4 c = cs[k * 4 + 2], d = cs[k * 4 + 3];
        float cv[DC] = {a.x, a.y, a.z, a.w, b.x, b.y, b.z, b.w,
                        c.x, c.y, c.z, c.w, d.x, d.y, d.z, d.w};
        float c2 = c2s[k];
#pragma unroll
        for (int r = 0; r < 4; r++) {
            float dot = 0.f;
#pragma unroll
            for (int j = 0; j < DC; j++) dot = fmaf(h[r][j], cv[j], dot);
            float dist = (h2[r] - 2.0f * dot) + c2;         // reference order
            if (dist < best[r]) { best[r] = dist; bidx[r] = codeBase + k; }
        }
    }

    // merge across code chunks: min score, ties -> smaller index (first-min)
#pragma unroll
    for (int r = 0; r < 4; r++) {
        unsigned long long key =
            ((unsigned long long)ordered_u32(best[r]) << 32) | (unsigned)bidx[r];
        atomicMin(&g_best[rowBase + r * 128 + tid], key);
    }
}

// ---------------- kernel 3: extract codes as float32 ------------------------
__global__ void k_out(float* __restrict__ out) {
    int i = blockIdx.x * blockDim.x + threadIdx.x;
    if (i < NROWS)
        out[i] = (float)(unsigned)(g_best[i] & 0xFFFFFFFFull);
}

// ---------------- launch -----------------------------------------------------
extern "C" void kernel_launch(void* const* d_in, const int* in_sizes, int n_in,
                              void* d_out, int out_size) {
    // Rank inputs by size: x (8388608) > codebook (131072) > proj_weight (8192)
    int a = 0, b = 1, c = 2;
    if (n_in >= 3) {
        if (in_sizes[a] < in_sizes[b]) { int t = a; a = b; b = t; }
        if (in_sizes[b] < in_sizes[c]) { int t = b; b = c; c = t; }
        if (in_sizes[a] < in_sizes[b]) { int t = a; a = b; b = t; }
    }
    const float* x  = (const float*)d_in[a];
    const float* cb = (const float*)d_in[b];
    const float* W  = (const float*)d_in[c];
    float* out = (float*)d_out;

    k_init<<<64, 256>>>(cb);
    k_proj<<<NROWS / 32, 256>>>(x, W);
    k_dist<<<dim3(32, 16), 128>>>((const float4*)cb);
    k_out<<<64, 256>>>(out);
}

// round 9
// speedup vs baseline: 1.8195x; 1.0601x over previous
#include <cuda_runtime.h>
#include <cstdint>

// Shapes (fixed by reference setup_inputs)
#define NROWS 16384   // B*L = 8*2048
#define DDIM  512
#define DC    16
#define KCB   8192
#define LN_EPS 1e-5f

// ---------------- device scratch (no allocation allowed) --------------------
__device__ float4             g_nh4[NROWS * 4];   // NEGATED LN(h) per row (1 MB)
__device__ float              g_hc2[KCB];         // 0.5 * sum c^2 per code
__device__ unsigned long long g_best[NROWS];      // packed (ordered_score<<32)|idx

__device__ __forceinline__ unsigned ordered_u32(float f) {
    unsigned u = __float_as_uint(f);
    return (u & 0x80000000u) ? ~u : (u | 0x80000000u);
}

// packed fp32x2 FMA (Blackwell): 2 FMAs per FMA-pipe instruction
__device__ __forceinline__ float2 ffma2(float2 a, float2 b, float2 c) {
    float2 d;
    asm("fma.rn.f32x2 %0, %1, %2, %3;"
        : "=l"(reinterpret_cast<unsigned long long&>(d))
        : "l"(reinterpret_cast<unsigned long long&>(a)),
          "l"(reinterpret_cast<unsigned long long&>(b)),
          "l"(reinterpret_cast<unsigned long long&>(c)));
    return d;
}

// ---------------- kernel 0: init (every launch; graph replays) --------------
__global__ void k_init(const float* __restrict__ cb) {
    int i = blockIdx.x * blockDim.x + threadIdx.x;
    if (i < NROWS) g_best[i] = 0xFFFFFFFFFFFFFFFFull;
    if (i < KCB) {
        const float4* c4 = (const float4*)(cb + (size_t)i * DC);
        float4 a = c4[0], b = c4[1], c = c4[2], d = c4[3];
        float cv[DC] = {a.x, a.y, a.z, a.w, b.x, b.y, b.z, b.w,
                        c.x, c.y, c.z, c.w, d.x, d.y, d.z, d.w};
        float c2 = 0.f;
#pragma unroll
        for (int j = 0; j < DC; j++) c2 = fmaf(cv[j], cv[j], c2);
        g_hc2[i] = 0.5f * c2;
    }
}

// ---------------- kernel 1: projection + LayerNorm (stores -h) --------------
// One warp per 4 rows; 8 warps/block; 512 blocks.
__global__ void __launch_bounds__(256) k_proj(
    const float* __restrict__ x, const float* __restrict__ W)
{
    const int warp = threadIdx.x >> 5;
    const int lane = threadIdx.x & 31;
    const int rowBase = (blockIdx.x * 8 + warp) * 4;

#pragma unroll
    for (int r = 0; r < 4; r++) {
        const int row = rowBase + r;
        float acc[DC];
#pragma unroll
        for (int j = 0; j < DC; j++) acc[j] = 0.f;

        const float* xrow = x + (size_t)row * DDIM;
#pragma unroll 4
        for (int d = lane; d < DDIM; d += 32) {
            float xv = xrow[d];
#pragma unroll
            for (int j = 0; j < DC; j++)
                acc[j] = fmaf(xv, W[j * DDIM + d], acc[j]);
        }
#pragma unroll
        for (int j = 0; j < DC; j++) {
#pragma unroll
            for (int ofs = 16; ofs > 0; ofs >>= 1)
                acc[j] += __shfl_xor_sync(0xFFFFFFFFu, acc[j], ofs);
        }

        float s = 0.f;
#pragma unroll
        for (int j = 0; j < DC; j++) s += acc[j];
        float mu = s * (1.0f / DC);
        float v = 0.f;
#pragma unroll
        for (int j = 0; j < DC; j++) { float d = acc[j] - mu; v = fmaf(d, d, v); }
        float denom = sqrtf(v * (1.0f / DC) + LN_EPS);
        float nh[DC];
#pragma unroll
        for (int j = 0; j < DC; j++) nh[j] = (mu - acc[j]) / denom;  // negated h

        if (lane < 4)
            g_nh4[(size_t)row * 4 + lane] =
                make_float4(nh[4 * lane], nh[4 * lane + 1], nh[4 * lane + 2], nh[4 * lane + 3]);
    }
}

// ---------------- kernel 2: distance + argmin (split-K, f32x2) --------------
// grid (32, 16): bx = 512-row tile, by = 512-code chunk. 128 thr, 4 rows/thr.
// score = 0.5||c||^2 - h.c  (argmin-equivalent; h2 constant per row dropped).
__global__ void __launch_bounds__(128, 4) k_dist(const float4* __restrict__ cb4) {
    __shared__ float4 cs[512 * 4];   // 512 codes x 16 floats (32 KB)
    __shared__ float  hc2s[512];

    const int tid = threadIdx.x;
    const int rowBase  = blockIdx.x * 512;
    const int codeBase = blockIdx.y * 512;

    for (int i = tid; i < 512 * 4; i += 128) cs[i] = cb4[codeBase * 4 + i];
    for (int i = tid; i < 512; i += 128) hc2s[i] = g_hc2[codeBase + i];
    __syncthreads();

    // this thread's 4 rows of -h, packed as float2 (register-resident)
    float2 nh[4][8];
#pragma unroll
    for (int r = 0; r < 4; r++) {
        const float4* p = &g_nh4[(size_t)(rowBase + r * 128 + tid) * 4];
#pragma unroll
        for (int q = 0; q < 4; q++) {
            float4 a = p[q];
            nh[r][2 * q]     = make_float2(a.x, a.y);
            nh[r][2 * q + 1] = make_float2(a.z, a.w);
        }
    }

    float best[4] = {3.4e38f, 3.4e38f, 3.4e38f, 3.4e38f};
    int   bidx[4] = {0x7FFFFFFF, 0x7FFFFFFF, 0x7FFFFFFF, 0x7FFFFFFF};

#pragma unroll 2
    for (int k = 0; k < 512; k++) {                 // broadcast LDS across warp
        float4 a = cs[k * 4 + 0], b = cs[k * 4 + 1];
        float4 c = cs[k * 4 + 2], d = cs[k * 4 + 3];
        float2 cv[8] = {
            make_float2(a.x, a.y), make_float2(a.z, a.w),
            make_float2(b.x, b.y), make_float2(b.z, b.w),
            make_float2(c.x, c.y), make_float2(c.z, c.w),
            make_float2(d.x, d.y), make_float2(d.z, d.w)};
        float hc2 = hc2s[k];
#pragma unroll
        for (int r = 0; r < 4; r++) {
            float2 acc = make_float2(hc2, 0.f);
#pragma unroll
            for (int j = 0; j < 8; j++) acc = ffma2(nh[r][j], cv[j], acc);
            float sc = acc.x + acc.y;
            if (sc < best[r]) { best[r] = sc; bidx[r] = codeBase + k; }
        }
    }

    // merge across code chunks: min score, ties -> smaller index (first-min)
#pragma unroll
    for (int r = 0; r < 4; r++) {
        unsigned long long key =
            ((unsigned long long)ordered_u32(best[r]) << 32) | (unsigned)bidx[r];
        atomicMin(&g_best[rowBase + r * 128 + tid], key);
    }
}

// ---------------- kernel 3: extract codes as float32 ------------------------
__global__ void k_out(float* __restrict__ out) {
    int i = blockIdx.x * blockDim.x + threadIdx.x;
    if (i < NROWS)
        out[i] = (float)(unsigned)(g_best[i] & 0xFFFFFFFFull);
}

// ---------------- launch -----------------------------------------------------
extern "C" void kernel_launch(void* const* d_in, const int* in_sizes, int n_in,
                              void* d_out, int out_size) {
    // Rank inputs by size: x (8388608) > codebook (131072) > proj_weight (8192)
    int a = 0, b = 1, c = 2;
    if (n_in >= 3) {
        if (in_sizes[a] < in_sizes[b]) { int t = a; a = b; b = t; }
        if (in_sizes[b] < in_sizes[c]) { int t = b; b = c; c = t; }
        if (in_sizes[a] < in_sizes[b]) { int t = a; a = b; b = t; }
    }
    const float* x  = (const float*)d_in[a];
    const float* cb = (const float*)d_in[b];
    const float* W  = (const float*)d_in[c];
    float* out = (float*)d_out;

    k_init<<<64, 256>>>(cb);
    k_proj<<<NROWS / 32, 256>>>(x, W);
    k_dist<<<dim3(32, 16), 128>>>((const float4*)cb);
    k_out<<<64, 256>>>(out);
}